// round 17
// baseline (speedup 1.0000x reference)
#include <cuda_runtime.h>

// MultiScaleHypercubeLayer fused kernel, R15 design (second resubmit — rounds
// 15 and 16 both hit GPU-broker acquisition timeouts; never measured).
// x: [16384, 2048] f32; W_to: [4,2048]; W_from: [2048,4]; scalars.
//
// vs R14 (49.6us): remove the 2nd barrier + the 12-idle-warp softmax bubble.
// After ONE barrier publishes s_part, EVERY warp redundantly computes the
// softmax for all G=4 tokens (2 tokens per pass: lanes 0-15 = corners of
// token A, lanes 16-31 = token B), broadcasts q via shuffles, and runs its
// epilogue slice immediately. s_part is double-buffered; s_q eliminated.
// Read/write DRAM-stream overlap from R14 retained (prefetch before bar).

#define D_MODEL 2048
#define THREADS 512
#define G 4
#define NB 4
#define T (G * NB)

extern __shared__ float4 s_x[];   // [G * THREADS] staged x (32 KB), thread-private slots

__global__ void __launch_bounds__(THREADS, 2)
hypercube_kernel(const float* __restrict__ x,
                 const float* __restrict__ W_to,
                 const float* __restrict__ W_from,
                 const float* __restrict__ log_temp,
                 const float* __restrict__ scale_p,
                 float* __restrict__ out)
{
    const int tid  = threadIdx.x;
    const int warp = tid >> 5;
    const int lane = tid & 31;
    const int d0   = tid * 4;

    // double-buffered per-warp partials: [buf][token-in-group][warp]
    __shared__ float4 s_part[2][G][16];

    const float temp  = fminf(fmaxf(expf(__ldg(log_temp)), 0.01f), 5.0f);
    const float inv_t = 1.0f / temp;
    const float scale = __ldg(scale_p);

    const size_t base = (size_t)blockIdx.x * T * D_MODEL + d0;
    const float* xp = x   + base;
    float*       op = out + base;

    // ---- weights resident in registers ----
    const float4 wt0 = __ldg(reinterpret_cast<const float4*>(W_to + 0 * D_MODEL + d0));
    const float4 wt1 = __ldg(reinterpret_cast<const float4*>(W_to + 1 * D_MODEL + d0));
    const float4 wt2 = __ldg(reinterpret_cast<const float4*>(W_to + 2 * D_MODEL + d0));
    const float4 wt3 = __ldg(reinterpret_cast<const float4*>(W_to + 3 * D_MODEL + d0));

    const float4 wf0 = __ldg(reinterpret_cast<const float4*>(W_from + (size_t)(d0 + 0) * 4));
    const float4 wf1 = __ldg(reinterpret_cast<const float4*>(W_from + (size_t)(d0 + 1) * 4));
    const float4 wf2 = __ldg(reinterpret_cast<const float4*>(W_from + (size_t)(d0 + 2) * 4));
    const float4 wf3 = __ldg(reinterpret_cast<const float4*>(W_from + (size_t)(d0 + 3) * 4));

    // ---- prefetch group 0 ----
    float4 xr[G];
#pragma unroll
    for (int u = 0; u < G; u++)
        xr[u] = *reinterpret_cast<const float4*>(xp + (size_t)u * D_MODEL);

#pragma unroll
    for (int g = 0; g < NB; g++) {
        const int buf = g & 1;

        // ---- projection + thread-private smem stage ----
#pragma unroll
        for (int u = 0; u < G; u++) {
            const float4 xv = xr[u];
            s_x[u * THREADS + tid] = xv;   // own slot; read back by same thread

            float z0 = xv.x * wt0.x + xv.y * wt0.y + xv.z * wt0.z + xv.w * wt0.w;
            float z1 = xv.x * wt1.x + xv.y * wt1.y + xv.z * wt1.z + xv.w * wt1.w;
            float z2 = xv.x * wt2.x + xv.y * wt2.y + xv.z * wt2.z + xv.w * wt2.w;
            float z3 = xv.x * wt3.x + xv.y * wt3.y + xv.z * wt3.z + xv.w * wt3.w;

            // transpose-reduce: 6 shuffles.
            float a01 = (lane & 1) ? z1 : z0;
            float b01 = (lane & 1) ? z0 : z1;
            a01 += __shfl_xor_sync(0xffffffffu, b01, 1);
            float a23 = (lane & 1) ? z3 : z2;
            float b23 = (lane & 1) ? z2 : z3;
            a23 += __shfl_xor_sync(0xffffffffu, b23, 1);
            float c = (lane & 2) ? a23 : a01;
            float d = (lane & 2) ? a01 : a23;
            c += __shfl_xor_sync(0xffffffffu, d, 2);
            c += __shfl_xor_sync(0xffffffffu, c, 4);
            c += __shfl_xor_sync(0xffffffffu, c, 8);
            c += __shfl_xor_sync(0xffffffffu, c, 16);

            if (lane < 4)
                reinterpret_cast<float*>(&s_part[buf][u][warp])[lane] = c;
        }

        // ---- issue next group's loads: overlap with bar/softmax/stores ----
        if (g + 1 < NB) {
#pragma unroll
            for (int u = 0; u < G; u++)
                xr[u] = *reinterpret_cast<const float4*>(
                    xp + (size_t)((g + 1) * G + u) * D_MODEL);
        }

        __syncthreads();   // publishes s_part[buf]; also fences s_part[buf] reuse

        // ---- every warp: softmax for all G tokens, 2 tokens per pass ----
#pragma unroll
        for (int p = 0; p < G / 2; p++) {
            const int half = lane >> 4;        // 0: token 2p, 1: token 2p+1
            const int hl   = lane & 15;        // corner index within token
            const int t    = 2 * p + half;

            // sum the 16 per-warp partials (4 butterfly levels within halves)
            float4 pz = s_part[buf][t][hl];
#pragma unroll
            for (int off = 1; off <= 8; off <<= 1) {
                pz.x += __shfl_xor_sync(0xffffffffu, pz.x, off);
                pz.y += __shfl_xor_sync(0xffffffffu, pz.y, off);
                pz.z += __shfl_xor_sync(0xffffffffu, pz.z, off);
                pz.w += __shfl_xor_sync(0xffffffffu, pz.w, off);
            }
            // corner hl: V[hl][j] = bit (3-j) of hl
            const float v0 = (float)((hl >> 3) & 1);
            const float v1 = (float)((hl >> 2) & 1);
            const float v2 = (float)((hl >> 1) & 1);
            const float v3 = (float)(hl & 1);

            const float dx = pz.x - v0, dy = pz.y - v1;
            const float dz = pz.z - v2, dw = pz.w - v3;
            const float dist = sqrtf(dx * dx + dy * dy + dz * dz + dw * dw);
            // dist >= 0 -> exp(-dist/temp) in (0,1]; no max-subtraction needed.
            const float w = __expf(-dist * inv_t);
            float ws = w;
            float q0 = w * v0, q1 = w * v1, q2 = w * v2, q3 = w * v3;
#pragma unroll
            for (int off = 1; off <= 8; off <<= 1) {
                ws += __shfl_xor_sync(0xffffffffu, ws, off);
                q0 += __shfl_xor_sync(0xffffffffu, q0, off);
                q1 += __shfl_xor_sync(0xffffffffu, q1, off);
                q2 += __shfl_xor_sync(0xffffffffu, q2, off);
                q3 += __shfl_xor_sync(0xffffffffu, q3, off);
            }
            const float sc = scale / ws;
            const float b0 = q0 * sc, b1 = q1 * sc, b2 = q2 * sc, b3 = q3 * sc;

            // broadcast both tokens' q to all lanes
            const float4 qA = make_float4(__shfl_sync(0xffffffffu, b0, 0),
                                          __shfl_sync(0xffffffffu, b1, 0),
                                          __shfl_sync(0xffffffffu, b2, 0),
                                          __shfl_sync(0xffffffffu, b3, 0));
            const float4 qB = make_float4(__shfl_sync(0xffffffffu, b0, 16),
                                          __shfl_sync(0xffffffffu, b1, 16),
                                          __shfl_sync(0xffffffffu, b2, 16),
                                          __shfl_sync(0xffffffffu, b3, 16));

            // ---- epilogue for tokens 2p and 2p+1 (x from own smem slot) ----
#pragma unroll
            for (int s = 0; s < 2; s++) {
                const int tt = 2 * p + s;
                const float4 q  = s ? qB : qA;
                const float4 xv = s_x[tt * THREADS + tid];
                float4 o;
                o.x = xv.x + q.x * wf0.x + q.y * wf0.y + q.z * wf0.z + q.w * wf0.w;
                o.y = xv.y + q.x * wf1.x + q.y * wf1.y + q.z * wf1.z + q.w * wf1.w;
                o.z = xv.z + q.x * wf2.x + q.y * wf2.y + q.z * wf2.z + q.w * wf2.w;
                o.w = xv.w + q.x * wf3.x + q.y * wf3.y + q.z * wf3.z + q.w * wf3.w;
                *reinterpret_cast<float4*>(op + (size_t)(g * G + tt) * D_MODEL) = o;
            }
        }
        // no second barrier: s_part is double-buffered, s_x slots thread-private
    }
}

extern "C" void kernel_launch(void* const* d_in, const int* in_sizes, int n_in,
                              void* d_out, int out_size)
{
    const float* x        = (const float*)d_in[0];
    const float* W_to     = (const float*)d_in[1];
    const float* W_from   = (const float*)d_in[2];
    const float* log_temp = (const float*)d_in[3];
    const float* scale    = (const float*)d_in[4];
    float* out = (float*)d_out;

    const int n_tokens = in_sizes[0] / D_MODEL;            // 16384
    const int blocks   = n_tokens / T;                     // 1024
    const int smem     = G * THREADS * sizeof(float4);     // 32 KB dynamic

    cudaFuncSetAttribute(hypercube_kernel,
                         cudaFuncAttributeMaxDynamicSharedMemorySize, smem);

    hypercube_kernel<<<blocks, THREADS, smem>>>(x, W_to, W_from, log_temp,
                                                scale, out);
}